// round 1
// baseline (speedup 1.0000x reference)
#include <cuda_runtime.h>

// ----------------------------------------------------------------------------
// BiBoSparseMoeBlock: top-2-of-8 MoE SwiGLU, fp32.
//   t = 4096 tokens, HID = 2048, INTER = 1024, E = 8, TOP_K = 2.
// Strategy: route first, compact token lists per expert, then grouped GEMMs
// over the 2*t = 8192 (token, expert) slots only (4x less FLOPs than dense).
// Inner loops use packed fma.rn.f32x2 (2x fp32 FMA rate vs scalar FFMA).
// ----------------------------------------------------------------------------

#define HID   2048
#define INTER 1024
#define NEXP  8
#define MAXT  4096
#define MAXSLOTS (2 * MAXT)
#define BK    16

typedef unsigned long long ull;

// ---- device scratch (static globals: allocation-free rule) -----------------
__device__ int   g_cnt[NEXP];
__device__ int   g_off[NEXP];
__device__ int   g_fill[NEXP];
__device__ int   g_perm[MAXSLOTS];      // slot -> token
__device__ float g_w[MAXSLOTS];         // slot -> routing weight
__device__ int   g_tidx[MAXT * 2];      // token -> top2 expert ids
__device__ float g_tw[MAXT * 2];        // token -> top2 weights
__device__ int   g_slot_of[MAXT * 2];   // token -> its 2 slots
__device__ float g_h[(size_t)MAXSLOTS * INTER];   // 32 MB: silu(g)*u
__device__ float g_y[(size_t)MAXSLOTS * HID];     // 64 MB: w * (h @ Wd^T)

// ---- packed f32x2 helpers ---------------------------------------------------
__device__ __forceinline__ ull dup2(float f) {
    unsigned int u = __float_as_uint(f);
    ull r;
    asm("mov.b64 %0, {%1, %1};" : "=l"(r) : "r"(u));
    return r;
}
__device__ __forceinline__ ull fma2(ull a, ull b, ull c) {
    ull d;
    asm("fma.rn.f32x2 %0, %1, %2, %3;" : "=l"(d) : "l"(a), "l"(b), "l"(c));
    return d;
}
__device__ __forceinline__ void unpack2(ull v, float& lo, float& hi) {
    unsigned int l, h;
    asm("mov.b64 {%0, %1}, %2;" : "=r"(l), "=r"(h) : "l"(v));
    lo = __uint_as_float(l);
    hi = __uint_as_float(h);
}
__device__ __forceinline__ float silu_f(float g) {
    return g / (1.0f + expf(-g));
}

// ---- kernel 1: zero counters ------------------------------------------------
__global__ void zero_counters_kernel() {
    int i = threadIdx.x;
    if (i < NEXP) { g_cnt[i] = 0; g_fill[i] = 0; }
}

// ---- kernel 2: router (logits, top-2, softmax, per-expert counts) -----------
__global__ void router_kernel(const float* __restrict__ x,
                              const float* __restrict__ Wr,
                              float* __restrict__ logits_out,
                              int write_logits) {
    const int t = blockIdx.x;
    const int warp = threadIdx.x >> 5;
    const int lane = threadIdx.x & 31;
    __shared__ float slog[NEXP];

    const float* xr = x + (size_t)t * HID;
    const float* wr = Wr + (size_t)warp * HID;
    float s = 0.0f;
    #pragma unroll 4
    for (int i = lane; i < HID; i += 32) s += xr[i] * wr[i];
    #pragma unroll
    for (int o = 16; o > 0; o >>= 1) s += __shfl_xor_sync(0xffffffffu, s, o);
    if (lane == 0) slog[warp] = s;
    __syncthreads();

    if (write_logits && threadIdx.x < NEXP)
        logits_out[t * NEXP + threadIdx.x] = slog[threadIdx.x];

    if (threadIdx.x == 0) {
        float v0 = -1e30f; int i0 = 0;
        #pragma unroll
        for (int i = 0; i < NEXP; i++) if (slog[i] > v0) { v0 = slog[i]; i0 = i; }
        float v1 = -1e30f; int i1 = 0;
        #pragma unroll
        for (int i = 0; i < NEXP; i++)
            if (i != i0 && slog[i] > v1) { v1 = slog[i]; i1 = i; }
        float ex = expf(v1 - v0);
        float inv = 1.0f / (1.0f + ex);
        g_tidx[2 * t] = i0;      g_tidx[2 * t + 1] = i1;
        g_tw[2 * t] = inv;       g_tw[2 * t + 1] = ex * inv;
        atomicAdd(&g_cnt[i0], 1);
        atomicAdd(&g_cnt[i1], 1);
    }
}

// ---- kernel 3: exclusive prefix over 8 counts --------------------------------
__global__ void offsets_kernel() {
    if (threadIdx.x == 0) {
        int o = 0;
        #pragma unroll
        for (int e = 0; e < NEXP; e++) { g_off[e] = o; o += g_cnt[e]; }
    }
}

// ---- kernel 4: scatter tokens into expert-compacted slot lists ---------------
__global__ void scatter_kernel(int T) {
    int t = blockIdx.x * blockDim.x + threadIdx.x;
    if (t >= T) return;
    #pragma unroll
    for (int j = 0; j < 2; j++) {
        int e = g_tidx[2 * t + j];
        int p = atomicAdd(&g_fill[e], 1);
        int slot = g_off[e] + p;
        g_perm[slot] = t;
        g_w[slot] = g_tw[2 * t + j];
        g_slot_of[2 * t + j] = slot;
    }
}

// ---- kernel 5: grouped gate+up GEMM, fused SiLU ------------------------------
// C[slot, f] tiles: BM=128 slots x BN=64 inter, K=2048, double-buffered smem.
#define GU_BM 128
#define GU_BN 64
__global__ __launch_bounds__(256, 2)
void gateup_kernel(const float* __restrict__ x,
                   const float* __restrict__ Wg,
                   const float* __restrict__ Wu) {
    const int e   = blockIdx.z;
    const int cnt = g_cnt[e];
    const int m0  = blockIdx.y * GU_BM;
    if (m0 >= cnt) return;
    const int rows = cnt - m0;                 // valid rows (<= 128)
    const int n0   = blockIdx.x * GU_BN;
    const int base = g_off[e] + m0;

    __shared__ __align__(16) float As [2][BK][GU_BM];
    __shared__ __align__(16) float Bgs[2][BK][GU_BN];
    __shared__ __align__(16) float Bus[2][BK][GU_BN];

    const int tid = threadIdx.x;
    // loader mapping: A tile 128x16 = 512 float4 (2/thread), B tiles 64x16 = 256 float4
    const int am = tid >> 2;
    const int ak = (tid & 3) << 2;
    const bool av0 = (am      < rows);
    const bool av1 = (am + 64 < rows);
    const float* arow0 = av0 ? (x + (size_t)g_perm[base + am     ] * HID + ak) : x;
    const float* arow1 = av1 ? (x + (size_t)g_perm[base + am + 64] * HID + ak) : x;
    const int bn = tid >> 2;
    const float* wgp = Wg + ((size_t)e * INTER + (n0 + bn)) * HID + ak;
    const float* wup = Wu + ((size_t)e * INTER + (n0 + bn)) * HID + ak;

    const float4 z4 = make_float4(0.f, 0.f, 0.f, 0.f);
    float4 ra0 = av0 ? *(const float4*)arow0 : z4;
    float4 ra1 = av1 ? *(const float4*)arow1 : z4;
    float4 rg  = *(const float4*)wgp;
    float4 ru  = *(const float4*)wup;
    #pragma unroll
    for (int i = 0; i < 4; i++) {
        As [0][ak + i][am]      = (&ra0.x)[i];
        As [0][ak + i][am + 64] = (&ra1.x)[i];
        Bgs[0][ak + i][bn]      = (&rg.x)[i];
        Bus[0][ak + i][bn]      = (&ru.x)[i];
    }
    __syncthreads();

    ull accg[8][2], accu[8][2];
    #pragma unroll
    for (int m = 0; m < 8; m++) {
        accg[m][0] = 0ull; accg[m][1] = 0ull;
        accu[m][0] = 0ull; accu[m][1] = 0ull;
    }

    const int ty = tid >> 4, tx = tid & 15;
    const int mb = ty * 8,   nb = tx * 4;
    const int KT = HID / BK;                   // 128

    for (int kt = 0; kt < KT; kt++) {
        const int cur = kt & 1, nxt = cur ^ 1;
        if (kt + 1 < KT) {
            const int ko = (kt + 1) * BK;
            ra0 = av0 ? *(const float4*)(arow0 + ko) : z4;
            ra1 = av1 ? *(const float4*)(arow1 + ko) : z4;
            rg  = *(const float4*)(wgp + ko);
            ru  = *(const float4*)(wup + ko);
        }
        #pragma unroll
        for (int k = 0; k < BK; k++) {
            float4 a0 = *(const float4*)&As[cur][k][mb];
            float4 a1 = *(const float4*)&As[cur][k][mb + 4];
            ulonglong2 bg = *(const ulonglong2*)&Bgs[cur][k][nb];
            ulonglong2 bu = *(const ulonglong2*)&Bus[cur][k][nb];
            ull ad[8];
            ad[0] = dup2(a0.x); ad[1] = dup2(a0.y); ad[2] = dup2(a0.z); ad[3] = dup2(a0.w);
            ad[4] = dup2(a1.x); ad[5] = dup2(a1.y); ad[6] = dup2(a1.z); ad[7] = dup2(a1.w);
            #pragma unroll
            for (int m = 0; m < 8; m++) {
                accg[m][0] = fma2(ad[m], bg.x, accg[m][0]);
                accg[m][1] = fma2(ad[m], bg.y, accg[m][1]);
                accu[m][0] = fma2(ad[m], bu.x, accu[m][0]);
                accu[m][1] = fma2(ad[m], bu.y, accu[m][1]);
            }
        }
        if (kt + 1 < KT) {
            #pragma unroll
            for (int i = 0; i < 4; i++) {
                As [nxt][ak + i][am]      = (&ra0.x)[i];
                As [nxt][ak + i][am + 64] = (&ra1.x)[i];
                Bgs[nxt][ak + i][bn]      = (&rg.x)[i];
                Bus[nxt][ak + i][bn]      = (&ru.x)[i];
            }
        }
        __syncthreads();
    }

    #pragma unroll
    for (int m = 0; m < 8; m++) {
        const int row = mb + m;
        if (row < rows) {
            float g0, g1, g2, g3, u0, u1, u2, u3;
            unpack2(accg[m][0], g0, g1); unpack2(accg[m][1], g2, g3);
            unpack2(accu[m][0], u0, u1); unpack2(accu[m][1], u2, u3);
            float4 h;
            h.x = silu_f(g0) * u0;
            h.y = silu_f(g1) * u1;
            h.z = silu_f(g2) * u2;
            h.w = silu_f(g3) * u3;
            *(float4*)(g_h + (size_t)(base + row) * INTER + n0 + nb) = h;
        }
    }
}

// ---- kernel 6: grouped down GEMM, scaled by routing weight --------------------
// y[slot, d] tiles: BM=128 slots x BN=128 hidden, K=1024.
#define DN_BM 128
#define DN_BN 128
__global__ __launch_bounds__(256, 2)
void down_kernel(const float* __restrict__ Wd) {
    const int e   = blockIdx.z;
    const int cnt = g_cnt[e];
    const int m0  = blockIdx.y * DN_BM;
    if (m0 >= cnt) return;
    const int rows = cnt - m0;
    const int n0   = blockIdx.x * DN_BN;
    const int base = g_off[e] + m0;

    __shared__ __align__(16) float As[2][BK][DN_BM];
    __shared__ __align__(16) float Bs[2][BK][DN_BN];

    const int tid = threadIdx.x;
    const int am = tid >> 2;
    const int ak = (tid & 3) << 2;
    const bool av0 = (am      < rows);
    const bool av1 = (am + 64 < rows);
    const float* a0p = av0 ? (g_h + (size_t)(base + am     ) * INTER + ak) : g_h;
    const float* a1p = av1 ? (g_h + (size_t)(base + am + 64) * INTER + ak) : g_h;
    const float* b0p = Wd + ((size_t)e * HID + n0 + am     ) * INTER + ak;
    const float* b1p = Wd + ((size_t)e * HID + n0 + am + 64) * INTER + ak;

    const float4 z4 = make_float4(0.f, 0.f, 0.f, 0.f);
    float4 ra0 = av0 ? *(const float4*)a0p : z4;
    float4 ra1 = av1 ? *(const float4*)a1p : z4;
    float4 rb0 = *(const float4*)b0p;
    float4 rb1 = *(const float4*)b1p;
    #pragma unroll
    for (int i = 0; i < 4; i++) {
        As[0][ak + i][am]      = (&ra0.x)[i];
        As[0][ak + i][am + 64] = (&ra1.x)[i];
        Bs[0][ak + i][am]      = (&rb0.x)[i];
        Bs[0][ak + i][am + 64] = (&rb1.x)[i];
    }
    __syncthreads();

    ull acc[8][4];
    #pragma unroll
    for (int m = 0; m < 8; m++)
        #pragma unroll
        for (int p = 0; p < 4; p++) acc[m][p] = 0ull;

    const int ty = tid >> 4, tx = tid & 15;
    const int mb = ty * 8,   nb = tx * 8;
    const int KT = INTER / BK;                 // 64

    for (int kt = 0; kt < KT; kt++) {
        const int cur = kt & 1, nxt = cur ^ 1;
        if (kt + 1 < KT) {
            const int ko = (kt + 1) * BK;
            ra0 = av0 ? *(const float4*)(a0p + ko) : z4;
            ra1 = av1 ? *(const float4*)(a1p + ko) : z4;
            rb0 = *(const float4*)(b0p + ko);
            rb1 = *(const float4*)(b1p + ko);
        }
        #pragma unroll
        for (int k = 0; k < BK; k++) {
            float4 a0 = *(const float4*)&As[cur][k][mb];
            float4 a1 = *(const float4*)&As[cur][k][mb + 4];
            ulonglong2 b0 = *(const ulonglong2*)&Bs[cur][k][nb];
            ulonglong2 b1 = *(const ulonglong2*)&Bs[cur][k][nb + 4];
            ull ad[8];
            ad[0] = dup2(a0.x); ad[1] = dup2(a0.y); ad[2] = dup2(a0.z); ad[3] = dup2(a0.w);
            ad[4] = dup2(a1.x); ad[5] = dup2(a1.y); ad[6] = dup2(a1.z); ad[7] = dup2(a1.w);
            #pragma unroll
            for (int m = 0; m < 8; m++) {
                acc[m][0] = fma2(ad[m], b0.x, acc[m][0]);
                acc[m][1] = fma2(ad[m], b0.y, acc[m][1]);
                acc[m][2] = fma2(ad[m], b1.x, acc[m][2]);
                acc[m][3] = fma2(ad[m], b1.y, acc[m][3]);
            }
        }
        if (kt + 1 < KT) {
            #pragma unroll
            for (int i = 0; i < 4; i++) {
                As[nxt][ak + i][am]      = (&ra0.x)[i];
                As[nxt][ak + i][am + 64] = (&ra1.x)[i];
                Bs[nxt][ak + i][am]      = (&rb0.x)[i];
                Bs[nxt][ak + i][am + 64] = (&rb1.x)[i];
            }
        }
        __syncthreads();
    }

    #pragma unroll
    for (int m = 0; m < 8; m++) {
        const int row = mb + m;
        if (row < rows) {
            const int slot = base + row;
            const float w = g_w[slot];
            float v0, v1, v2, v3, v4, v5, v6, v7;
            unpack2(acc[m][0], v0, v1); unpack2(acc[m][1], v2, v3);
            unpack2(acc[m][2], v4, v5); unpack2(acc[m][3], v6, v7);
            float* yp = g_y + (size_t)slot * HID + n0 + nb;
            float4 r0 = make_float4(w * v0, w * v1, w * v2, w * v3);
            float4 r1 = make_float4(w * v4, w * v5, w * v6, w * v7);
            *(float4*)(yp)     = r0;
            *(float4*)(yp + 4) = r1;
        }
    }
}

// ---- kernel 7: deterministic combine of the token's 2 slots -------------------
__global__ void combine_kernel(float* __restrict__ out, int T) {
    const int gid = blockIdx.x * blockDim.x + threadIdx.x;
    const int per_tok = HID / 4;
    if (gid >= T * per_tok) return;
    const int t = gid / per_tok;
    const int c = gid - t * per_tok;
    const int s0 = g_slot_of[2 * t];
    const int s1 = g_slot_of[2 * t + 1];
    float4 a = ((const float4*)(g_y + (size_t)s0 * HID))[c];
    float4 b = ((const float4*)(g_y + (size_t)s1 * HID))[c];
    float4 r = make_float4(a.x + b.x, a.y + b.y, a.z + b.z, a.w + b.w);
    ((float4*)(out + (size_t)t * HID))[c] = r;
}

// ---- launch ------------------------------------------------------------------
extern "C" void kernel_launch(void* const* d_in, const int* in_sizes, int n_in,
                              void* d_out, int out_size) {
    if (n_in < 5) return;
    const float* x  = (const float*)d_in[0];
    const float* Wr = (const float*)d_in[1];
    const float* Wg = (const float*)d_in[2];
    const float* Wu = (const float*)d_in[3];
    const float* Wd = (const float*)d_in[4];
    float* out = (float*)d_out;

    int T = in_sizes[0] / HID;
    if (T > MAXT) T = MAXT;

    const int write_logits = (out_size >= T * HID + T * NEXP);
    float* logits = out + (size_t)T * HID;

    zero_counters_kernel<<<1, 32>>>();
    router_kernel<<<T, 256>>>(x, Wr, logits, write_logits);
    offsets_kernel<<<1, 32>>>();
    scatter_kernel<<<(T + 255) / 256, 256>>>(T);
    gateup_kernel<<<dim3(INTER / GU_BN, (T + GU_BM - 1) / GU_BM, NEXP), 256>>>(x, Wg, Wu);
    down_kernel<<<dim3(HID / DN_BN, (T + DN_BM - 1) / DN_BM, NEXP), 256>>>(Wd);
    combine_kernel<<<(T * (HID / 4) + 255) / 256, 256>>>(out, T);
}

// round 3
// speedup vs baseline: 1.5173x; 1.5173x over previous
#include <cuda_runtime.h>
#include <cuda_bf16.h>
#include <cstdint>

// ============================================================================
// BiBoSparseMoeBlock: top-2-of-8 MoE SwiGLU, fp32 in/out.
// Round 3: baseline-PTX tensor cores (mma.sync m16n8k16 bf16) with hi/lo
// bf16 split (3 MMAs) emulating fp32 GEMM. No 'a'-suffix PTX anywhere.
// ============================================================================

#define HID   2048
#define INTER 1024
#define NEXP  8
#define MAXT  4096
#define MAXSLOTS (2 * MAXT)

typedef unsigned int u32;

// ---- device scratch ---------------------------------------------------------
__device__ int   g_cnt[NEXP];
__device__ int   g_off[NEXP];
__device__ int   g_fill[NEXP];
__device__ int   g_perm[MAXSLOTS];
__device__ float g_w[MAXSLOTS];
__device__ int   g_tidx[MAXT * 2];
__device__ float g_tw[MAXT * 2];
__device__ int   g_slot_of[MAXT * 2];

__device__ __nv_bfloat16 g_Xh[(size_t)MAXT * HID];
__device__ __nv_bfloat16 g_Xl[(size_t)MAXT * HID];
__device__ __nv_bfloat16 g_Wgh[(size_t)NEXP * INTER * HID];
__device__ __nv_bfloat16 g_Wgl[(size_t)NEXP * INTER * HID];
__device__ __nv_bfloat16 g_Wuh[(size_t)NEXP * INTER * HID];
__device__ __nv_bfloat16 g_Wul[(size_t)NEXP * INTER * HID];
__device__ __nv_bfloat16 g_Wdh[(size_t)NEXP * HID * INTER];
__device__ __nv_bfloat16 g_Wdl[(size_t)NEXP * HID * INTER];
__device__ __nv_bfloat16 g_Hh[(size_t)MAXSLOTS * INTER];
__device__ __nv_bfloat16 g_Hl[(size_t)MAXSLOTS * INTER];
__device__ float g_y[(size_t)MAXSLOTS * HID];

// ---- PTX helpers (all baseline, sm_80-era) -----------------------------------
__device__ __forceinline__ u32 smem_u32(const void* p) {
    u32 a;
    asm("{ .reg .u64 t; cvta.to.shared.u64 t, %1; cvt.u32.u64 %0, t; }" : "=r"(a) : "l"(p));
    return a;
}
__device__ __forceinline__ void cpa16(u32 dst, const void* src) {
    asm volatile("cp.async.cg.shared.global [%0], [%1], 16;" :: "r"(dst), "l"(src));
}
#define CPA_COMMIT() asm volatile("cp.async.commit_group;" ::: "memory")
#define CPA_WAIT1()  asm volatile("cp.async.wait_group 1;" ::: "memory")
#define CPA_WAIT0()  asm volatile("cp.async.wait_group 0;" ::: "memory")

__device__ __forceinline__ void ldsm4(u32* r, u32 addr) {
    asm volatile("ldmatrix.sync.aligned.m8n8.x4.shared.b16 {%0,%1,%2,%3}, [%4];"
                 : "=r"(r[0]), "=r"(r[1]), "=r"(r[2]), "=r"(r[3]) : "r"(addr));
}
__device__ __forceinline__ void mma16816(float* c, const u32* a, u32 b0, u32 b1) {
    asm volatile(
        "mma.sync.aligned.m16n8k16.row.col.f32.bf16.bf16.f32 "
        "{%0,%1,%2,%3}, {%4,%5,%6,%7}, {%8,%9}, {%0,%1,%2,%3};"
        : "+f"(c[0]), "+f"(c[1]), "+f"(c[2]), "+f"(c[3])
        : "r"(a[0]), "r"(a[1]), "r"(a[2]), "r"(a[3]), "r"(b0), "r"(b1));
}

// ---- smem geometry: BK=32 bf16 => 64B data per row, pitch 80B ------------------
// bank-group(r,c16) = (5r + c) mod 8 : permutation in r => conflict-free for
// both cp.async quadrant writes and ldmatrix 8-row reads.
#define PITCH 80
#define MAT_BYTES (128 * PITCH)     // 10240
#define OFF_AH 0
#define OFF_AL (1 * MAT_BYTES)
#define OFF_BH (2 * MAT_BYTES)
#define OFF_BL (3 * MAT_BYTES)
#define STAGE_BYTES (4 * MAT_BYTES) // 40960
#define NSTAGE 3
#define SMEM_DYN (NSTAGE * STAGE_BYTES)  // 122880

// ---- small kernels -------------------------------------------------------------
__global__ void zero_counters_kernel() {
    int i = threadIdx.x;
    if (i < NEXP) { g_cnt[i] = 0; g_fill[i] = 0; }
}

__global__ void router_kernel(const float* __restrict__ x,
                              const float* __restrict__ Wr,
                              float* __restrict__ logits_out, int write_logits) {
    const int t = blockIdx.x;
    const int warp = threadIdx.x >> 5;
    const int lane = threadIdx.x & 31;
    __shared__ float slog[NEXP];
    const float* xr = x + (size_t)t * HID;
    const float* wr = Wr + (size_t)warp * HID;
    float s = 0.0f;
    #pragma unroll 4
    for (int i = lane; i < HID; i += 32) s += xr[i] * wr[i];
    #pragma unroll
    for (int o = 16; o > 0; o >>= 1) s += __shfl_xor_sync(0xffffffffu, s, o);
    if (lane == 0) slog[warp] = s;
    __syncthreads();
    if (write_logits && threadIdx.x < NEXP)
        logits_out[t * NEXP + threadIdx.x] = slog[threadIdx.x];
    if (threadIdx.x == 0) {
        float v0 = -1e30f; int i0 = 0;
        #pragma unroll
        for (int i = 0; i < NEXP; i++) if (slog[i] > v0) { v0 = slog[i]; i0 = i; }
        float v1 = -1e30f; int i1 = 0;
        #pragma unroll
        for (int i = 0; i < NEXP; i++)
            if (i != i0 && slog[i] > v1) { v1 = slog[i]; i1 = i; }
        float ex = expf(v1 - v0);
        float inv = 1.0f / (1.0f + ex);
        g_tidx[2 * t] = i0; g_tidx[2 * t + 1] = i1;
        g_tw[2 * t] = inv;  g_tw[2 * t + 1] = ex * inv;
        atomicAdd(&g_cnt[i0], 1);
        atomicAdd(&g_cnt[i1], 1);
    }
}

__global__ void offsets_kernel() {
    if (threadIdx.x == 0) {
        int o = 0;
        #pragma unroll
        for (int e = 0; e < NEXP; e++) { g_off[e] = o; o += g_cnt[e]; }
    }
}

__global__ void scatter_kernel(int T) {
    int t = blockIdx.x * blockDim.x + threadIdx.x;
    if (t >= T) return;
    #pragma unroll
    for (int j = 0; j < 2; j++) {
        int e = g_tidx[2 * t + j];
        int p = atomicAdd(&g_fill[e], 1);
        int slot = g_off[e] + p;
        g_perm[slot] = t;
        g_w[slot] = g_tw[2 * t + j];
        g_slot_of[2 * t + j] = slot;
    }
}

// fp32 -> (bf16 hi, bf16 lo) split
__global__ void split_kernel(const float* __restrict__ src, int which, int n4) {
    int i = blockIdx.x * blockDim.x + threadIdx.x;
    if (i >= n4) return;
    __nv_bfloat16 *hi, *lo;
    switch (which) {
        case 0: hi = g_Xh;  lo = g_Xl;  break;
        case 1: hi = g_Wgh; lo = g_Wgl; break;
        case 2: hi = g_Wuh; lo = g_Wul; break;
        default: hi = g_Wdh; lo = g_Wdl; break;
    }
    float4 v = ((const float4*)src)[i];
    __nv_bfloat162 A = __floats2bfloat162_rn(v.x, v.y);
    __nv_bfloat162 B = __floats2bfloat162_rn(v.z, v.w);
    __nv_bfloat162 Ar = __floats2bfloat162_rn(v.x - __low2float(A), v.y - __high2float(A));
    __nv_bfloat162 Br = __floats2bfloat162_rn(v.z - __low2float(B), v.w - __high2float(B));
    uint2 H, L;
    H.x = *(u32*)&A;  H.y = *(u32*)&B;
    L.x = *(u32*)&Ar; L.y = *(u32*)&Br;
    ((uint2*)hi)[i] = H;
    ((uint2*)lo)[i] = L;
}

// ---- GEMM 1: gate+up. CTA tile: 128 slots x (64 gate + 64 up), K = 2048 --------
__global__ __launch_bounds__(256, 1) void gateup_mma_kernel() {
    const int e   = blockIdx.z;
    const int cnt = g_cnt[e];
    const int m0  = blockIdx.y * 128;
    if (m0 >= cnt) return;
    const int rows = min(cnt - m0, 128);
    const int base = g_off[e] + m0;
    const int n0   = blockIdx.x * 64;

    extern __shared__ char dsm[];
    const u32 sm0 = smem_u32(dsm);

    const int tid  = threadIdx.x;
    const int lane = tid & 31;
    const int wid  = tid >> 5;
    const int wm   = wid >> 2;          // 0..1 : 64 rows
    const int wn   = wid & 3;           // 0..3 : 32 cols

    // ---- per-thread load setup (8 cp.async / stage) ----
    const int r   = tid & 127;
    const int hl  = tid >> 7;           // 0 = hi set, 1 = lo set
    const int rr  = min(r, rows - 1);
    const __nv_bfloat16* asrc =
        (hl ? g_Xl : g_Xh) + (size_t)g_perm[base + rr] * HID;
    const __nv_bfloat16* bsrc;
    {
        const size_t wrow = (size_t)e * INTER + n0 + (r & 63);
        if (r < 64) bsrc = (hl ? g_Wgl : g_Wgh) + wrow * HID;
        else        bsrc = (hl ? g_Wul : g_Wuh) + wrow * HID;
    }
    const u32 adst = sm0 + (hl ? OFF_AL : OFF_AH) + (u32)r * PITCH;
    const u32 bdst = sm0 + (hl ? OFF_BL : OFF_BH) + (u32)r * PITCH;

    // ---- ldmatrix address bases ----
    const u32 a_off = (u32)(wm * 64 + (lane & 7) + ((lane >> 3) & 1) * 8) * PITCH
                    + (u32)(lane >> 4) * 16;
    const u32 b_off = (u32)(wn * 32 + (lane & 7) + (lane >> 4) * 8) * PITCH
                    + (u32)((lane >> 3) & 1) * 16;

    float acc[4][4][4];
    #pragma unroll
    for (int i = 0; i < 4; i++)
        #pragma unroll
        for (int j = 0; j < 4; j++)
            #pragma unroll
            for (int k = 0; k < 4; k++) acc[i][j][k] = 0.0f;

    const int KT = HID / 32;            // 64 stages

    // prologue: stages 0,1
    #pragma unroll
    for (int p = 0; p < NSTAGE - 1; p++) {
        const u32 sb = (u32)p * STAGE_BYTES;
        const __nv_bfloat16* a = asrc + p * 32;
        const __nv_bfloat16* b = bsrc + p * 32;
        #pragma unroll
        for (int c = 0; c < 4; c++) {
            cpa16(adst + sb + c * 16, a + c * 8);
            cpa16(bdst + sb + c * 16, b + c * 8);
        }
        CPA_COMMIT();
    }

    #pragma unroll 1
    for (int kt = 0; kt < KT; kt++) {
        CPA_WAIT1();
        __syncthreads();
        if (kt + NSTAGE - 1 < KT) {
            const u32 sb = (u32)((kt + NSTAGE - 1) % NSTAGE) * STAGE_BYTES;
            const __nv_bfloat16* a = asrc + (kt + NSTAGE - 1) * 32;
            const __nv_bfloat16* b = bsrc + (kt + NSTAGE - 1) * 32;
            #pragma unroll
            for (int c = 0; c < 4; c++) {
                cpa16(adst + sb + c * 16, a + c * 8);
                cpa16(bdst + sb + c * 16, b + c * 8);
            }
            CPA_COMMIT();
        }
        const u32 sb = sm0 + (u32)(kt % NSTAGE) * STAGE_BYTES;
        #pragma unroll
        for (int ks = 0; ks < 2; ks++) {
            u32 ah[4][4], al[4][4], bh[2][4], bl[2][4];
            #pragma unroll
            for (int mi = 0; mi < 4; mi++) {
                ldsm4(ah[mi], sb + OFF_AH + a_off + (u32)(mi * 16 * PITCH) + (u32)(ks * 32));
                ldsm4(al[mi], sb + OFF_AL + a_off + (u32)(mi * 16 * PITCH) + (u32)(ks * 32));
            }
            #pragma unroll
            for (int nh = 0; nh < 2; nh++) {
                ldsm4(bh[nh], sb + OFF_BH + b_off + (u32)(nh * 16 * PITCH) + (u32)(ks * 32));
                ldsm4(bl[nh], sb + OFF_BL + b_off + (u32)(nh * 16 * PITCH) + (u32)(ks * 32));
            }
            #pragma unroll
            for (int mi = 0; mi < 4; mi++) {
                #pragma unroll
                for (int ni = 0; ni < 4; ni++) {
                    const int q = ni >> 1, s = (ni & 1) * 2;
                    mma16816(acc[mi][ni], ah[mi], bh[q][s], bh[q][s + 1]);
                    mma16816(acc[mi][ni], ah[mi], bl[q][s], bl[q][s + 1]);
                    mma16816(acc[mi][ni], al[mi], bh[q][s], bh[q][s + 1]);
                }
            }
        }
        __syncthreads();
    }
    CPA_WAIT0();
    __syncthreads();

    // ---- epilogue: exchange via smem, fuse silu(g)*u, split to bf16 hi/lo ----
    float* S = (float*)dsm;             // 128 x 132 pitch
    #pragma unroll
    for (int mi = 0; mi < 4; mi++) {
        const int r0 = wm * 64 + mi * 16 + (lane >> 2);
        #pragma unroll
        for (int ni = 0; ni < 4; ni++) {
            const int c0 = wn * 32 + ni * 8 + 2 * (lane & 3);
            *(float2*)(S + (size_t)r0 * 132 + c0)       = make_float2(acc[mi][ni][0], acc[mi][ni][1]);
            *(float2*)(S + (size_t)(r0 + 8) * 132 + c0) = make_float2(acc[mi][ni][2], acc[mi][ni][3]);
        }
    }
    __syncthreads();
    {
        const int row = tid >> 1;
        const int qh  = (tid & 1) * 32;
        if (row < rows) {
            u32 ph[16], pl[16];
            #pragma unroll
            for (int p = 0; p < 16; p++) {
                float g0 = S[(size_t)row * 132 + qh + 2 * p];
                float g1 = S[(size_t)row * 132 + qh + 2 * p + 1];
                float u0 = S[(size_t)row * 132 + 64 + qh + 2 * p];
                float u1 = S[(size_t)row * 132 + 64 + qh + 2 * p + 1];
                float h0 = (g0 / (1.0f + expf(-g0))) * u0;
                float h1 = (g1 / (1.0f + expf(-g1))) * u1;
                __nv_bfloat162 A = __floats2bfloat162_rn(h0, h1);
                __nv_bfloat162 B = __floats2bfloat162_rn(h0 - __low2float(A), h1 - __high2float(A));
                ph[p] = *(u32*)&A;
                pl[p] = *(u32*)&B;
            }
            u32* dh = (u32*)(g_Hh + (size_t)(base + row) * INTER + n0 + qh);
            u32* dl = (u32*)(g_Hl + (size_t)(base + row) * INTER + n0 + qh);
            #pragma unroll
            for (int q = 0; q < 4; q++) {
                ((uint4*)dh)[q] = make_uint4(ph[4*q], ph[4*q+1], ph[4*q+2], ph[4*q+3]);
                ((uint4*)dl)[q] = make_uint4(pl[4*q], pl[4*q+1], pl[4*q+2], pl[4*q+3]);
            }
        }
    }
}

// ---- GEMM 2: down. CTA tile: 128 slots x 128 hid, K = 1024 ---------------------
__global__ __launch_bounds__(256, 1) void down_mma_kernel() {
    const int e   = blockIdx.z;
    const int cnt = g_cnt[e];
    const int m0  = blockIdx.y * 128;
    if (m0 >= cnt) return;
    const int rows = min(cnt - m0, 128);
    const int base = g_off[e] + m0;
    const int n0   = blockIdx.x * 128;

    extern __shared__ char dsm[];
    const u32 sm0 = smem_u32(dsm);

    const int tid  = threadIdx.x;
    const int lane = tid & 31;
    const int wid  = tid >> 5;
    const int wm   = wid >> 2;
    const int wn   = wid & 3;

    const int r  = tid & 127;
    const int hl = tid >> 7;
    const int rr = min(r, rows - 1);
    const __nv_bfloat16* asrc = (hl ? g_Hl : g_Hh) + (size_t)(base + rr) * INTER;
    const __nv_bfloat16* bsrc =
        (hl ? g_Wdl : g_Wdh) + ((size_t)e * HID + n0 + r) * INTER;
    const u32 adst = sm0 + (hl ? OFF_AL : OFF_AH) + (u32)r * PITCH;
    const u32 bdst = sm0 + (hl ? OFF_BL : OFF_BH) + (u32)r * PITCH;

    const u32 a_off = (u32)(wm * 64 + (lane & 7) + ((lane >> 3) & 1) * 8) * PITCH
                    + (u32)(lane >> 4) * 16;
    const u32 b_off = (u32)(wn * 32 + (lane & 7) + (lane >> 4) * 8) * PITCH
                    + (u32)((lane >> 3) & 1) * 16;

    float acc[4][4][4];
    #pragma unroll
    for (int i = 0; i < 4; i++)
        #pragma unroll
        for (int j = 0; j < 4; j++)
            #pragma unroll
            for (int k = 0; k < 4; k++) acc[i][j][k] = 0.0f;

    const int KT = INTER / 32;          // 32 stages

    #pragma unroll
    for (int p = 0; p < NSTAGE - 1; p++) {
        const u32 sb = (u32)p * STAGE_BYTES;
        const __nv_bfloat16* a = asrc + p * 32;
        const __nv_bfloat16* b = bsrc + p * 32;
        #pragma unroll
        for (int c = 0; c < 4; c++) {
            cpa16(adst + sb + c * 16, a + c * 8);
            cpa16(bdst + sb + c * 16, b + c * 8);
        }
        CPA_COMMIT();
    }

    #pragma unroll 1
    for (int kt = 0; kt < KT; kt++) {
        CPA_WAIT1();
        __syncthreads();
        if (kt + NSTAGE - 1 < KT) {
            const u32 sb = (u32)((kt + NSTAGE - 1) % NSTAGE) * STAGE_BYTES;
            const __nv_bfloat16* a = asrc + (kt + NSTAGE - 1) * 32;
            const __nv_bfloat16* b = bsrc + (kt + NSTAGE - 1) * 32;
            #pragma unroll
            for (int c = 0; c < 4; c++) {
                cpa16(adst + sb + c * 16, a + c * 8);
                cpa16(bdst + sb + c * 16, b + c * 8);
            }
            CPA_COMMIT();
        }
        const u32 sb = sm0 + (u32)(kt % NSTAGE) * STAGE_BYTES;
        #pragma unroll
        for (int ks = 0; ks < 2; ks++) {
            u32 ah[4][4], al[4][4], bh[2][4], bl[2][4];
            #pragma unroll
            for (int mi = 0; mi < 4; mi++) {
                ldsm4(ah[mi], sb + OFF_AH + a_off + (u32)(mi * 16 * PITCH) + (u32)(ks * 32));
                ldsm4(al[mi], sb + OFF_AL + a_off + (u32)(mi * 16 * PITCH) + (u32)(ks * 32));
            }
            #pragma unroll
            for (int nh = 0; nh < 2; nh++) {
                ldsm4(bh[nh], sb + OFF_BH + b_off + (u32)(nh * 16 * PITCH) + (u32)(ks * 32));
                ldsm4(bl[nh], sb + OFF_BL + b_off + (u32)(nh * 16 * PITCH) + (u32)(ks * 32));
            }
            #pragma unroll
            for (int mi = 0; mi < 4; mi++) {
                #pragma unroll
                for (int ni = 0; ni < 4; ni++) {
                    const int q = ni >> 1, s = (ni & 1) * 2;
                    mma16816(acc[mi][ni], ah[mi], bh[q][s], bh[q][s + 1]);
                    mma16816(acc[mi][ni], ah[mi], bl[q][s], bl[q][s + 1]);
                    mma16816(acc[mi][ni], al[mi], bh[q][s], bh[q][s + 1]);
                }
            }
        }
        __syncthreads();
    }

    // ---- epilogue: scale by routing weight, store f32 ----
    #pragma unroll
    for (int mi = 0; mi < 4; mi++) {
        const int r0 = wm * 64 + mi * 16 + (lane >> 2);
        const int r1 = r0 + 8;
        #pragma unroll
        for (int ni = 0; ni < 4; ni++) {
            const int c0 = wn * 32 + ni * 8 + 2 * (lane & 3);
            if (r0 < rows) {
                const float w0 = g_w[base + r0];
                *(float2*)(g_y + (size_t)(base + r0) * HID + n0 + c0) =
                    make_float2(w0 * acc[mi][ni][0], w0 * acc[mi][ni][1]);
            }
            if (r1 < rows) {
                const float w1 = g_w[base + r1];
                *(float2*)(g_y + (size_t)(base + r1) * HID + n0 + c0) =
                    make_float2(w1 * acc[mi][ni][2], w1 * acc[mi][ni][3]);
            }
        }
    }
}

// ---- combine: out[t] = y[slot0] + y[slot1] -------------------------------------
__global__ void combine_kernel(float* __restrict__ out, int T) {
    const int gid = blockIdx.x * blockDim.x + threadIdx.x;
    const int per_tok = HID / 4;
    if (gid >= T * per_tok) return;
    const int t = gid / per_tok;
    const int c = gid - t * per_tok;
    const int s0 = g_slot_of[2 * t];
    const int s1 = g_slot_of[2 * t + 1];
    float4 a = ((const float4*)(g_y + (size_t)s0 * HID))[c];
    float4 b = ((const float4*)(g_y + (size_t)s1 * HID))[c];
    ((float4*)(out + (size_t)t * HID))[c] =
        make_float4(a.x + b.x, a.y + b.y, a.z + b.z, a.w + b.w);
}

// ---- launch ---------------------------------------------------------------------
extern "C" void kernel_launch(void* const* d_in, const int* in_sizes, int n_in,
                              void* d_out, int out_size) {
    if (n_in < 5) return;
    const float* x  = (const float*)d_in[0];
    const float* Wr = (const float*)d_in[1];
    const float* Wg = (const float*)d_in[2];
    const float* Wu = (const float*)d_in[3];
    const float* Wd = (const float*)d_in[4];
    float* out = (float*)d_out;

    int T = in_sizes[0] / HID;
    if (T > MAXT) T = MAXT;

    static int attrs_set = 0;
    cudaFuncSetAttribute(gateup_mma_kernel, cudaFuncAttributeMaxDynamicSharedMemorySize, SMEM_DYN);
    cudaFuncSetAttribute(down_mma_kernel,   cudaFuncAttributeMaxDynamicSharedMemorySize, SMEM_DYN);
    (void)attrs_set;

    const int write_logits = (out_size >= T * HID + T * NEXP);
    float* logits = out + (size_t)T * HID;

    zero_counters_kernel<<<1, 32>>>();
    router_kernel<<<T, 256>>>(x, Wr, logits, write_logits);
    offsets_kernel<<<1, 32>>>();
    scatter_kernel<<<(T + 255) / 256, 256>>>(T);

    const int nw4 = NEXP * INTER * HID / 4;
    split_kernel<<<(T * HID / 4 + 255) / 256, 256>>>(x,  0, T * HID / 4);
    split_kernel<<<(nw4 + 255) / 256, 256>>>(Wg, 1, nw4);
    split_kernel<<<(nw4 + 255) / 256, 256>>>(Wu, 2, nw4);
    split_kernel<<<(nw4 + 255) / 256, 256>>>(Wd, 3, nw4);

    gateup_mma_kernel<<<dim3(INTER / 64, MAXSLOTS / 128, NEXP), 256, SMEM_DYN>>>();
    down_mma_kernel<<<dim3(HID / 128, MAXSLOTS / 128, NEXP), 256, SMEM_DYN>>>();

    combine_kernel<<<(T * (HID / 4) + 255) / 256, 256>>>(out, T);
}

// round 4
// speedup vs baseline: 2.0710x; 1.3649x over previous
#include <cuda_runtime.h>
#include <cuda_bf16.h>
#include <cstdint>

// ============================================================================
// BiBoSparseMoeBlock: top-2-of-8 MoE SwiGLU, fp32 in/out.
// Round 4: mma.sync bf16 hi/lo split (3 MMAs), 2 CTAs/SM (30KB stages x3),
// single __syncthreads per k-step, fused split kernel, safe tail wait.
// ============================================================================

#define HID   2048
#define INTER 1024
#define NEXP  8
#define MAXT  4096
#define MAXSLOTS (2 * MAXT)

typedef unsigned int u32;

// ---- device scratch ---------------------------------------------------------
__device__ int   g_cnt[NEXP];
__device__ int   g_off[NEXP];
__device__ int   g_fill[NEXP];
__device__ int   g_perm[MAXSLOTS];
__device__ float g_w[MAXSLOTS];
__device__ int   g_tidx[MAXT * 2];
__device__ float g_tw[MAXT * 2];
__device__ int   g_slot_of[MAXT * 2];

__device__ __nv_bfloat16 g_Xh[(size_t)MAXT * HID];
__device__ __nv_bfloat16 g_Xl[(size_t)MAXT * HID];
__device__ __nv_bfloat16 g_Wgh[(size_t)NEXP * INTER * HID];
__device__ __nv_bfloat16 g_Wgl[(size_t)NEXP * INTER * HID];
__device__ __nv_bfloat16 g_Wuh[(size_t)NEXP * INTER * HID];
__device__ __nv_bfloat16 g_Wul[(size_t)NEXP * INTER * HID];
__device__ __nv_bfloat16 g_Wdh[(size_t)NEXP * HID * INTER];
__device__ __nv_bfloat16 g_Wdl[(size_t)NEXP * HID * INTER];
__device__ __nv_bfloat16 g_Hh[(size_t)MAXSLOTS * INTER];
__device__ __nv_bfloat16 g_Hl[(size_t)MAXSLOTS * INTER];
__device__ float g_y[(size_t)MAXSLOTS * HID];

// ---- PTX helpers (baseline sm_80-era only) -------------------------------------
__device__ __forceinline__ u32 smem_u32(const void* p) {
    u32 a;
    asm("{ .reg .u64 t; cvta.to.shared.u64 t, %1; cvt.u32.u64 %0, t; }" : "=r"(a) : "l"(p));
    return a;
}
__device__ __forceinline__ void cpa16(u32 dst, const void* src) {
    asm volatile("cp.async.cg.shared.global [%0], [%1], 16;" :: "r"(dst), "l"(src));
}
#define CPA_COMMIT() asm volatile("cp.async.commit_group;" ::: "memory")
#define CPA_WAIT1()  asm volatile("cp.async.wait_group 1;" ::: "memory")
#define CPA_WAIT0()  asm volatile("cp.async.wait_group 0;" ::: "memory")

__device__ __forceinline__ void ldsm4(u32* r, u32 addr) {
    asm volatile("ldmatrix.sync.aligned.m8n8.x4.shared.b16 {%0,%1,%2,%3}, [%4];"
                 : "=r"(r[0]), "=r"(r[1]), "=r"(r[2]), "=r"(r[3]) : "r"(addr));
}
__device__ __forceinline__ void mma16816(float* c, const u32* a, u32 b0, u32 b1) {
    asm volatile(
        "mma.sync.aligned.m16n8k16.row.col.f32.bf16.bf16.f32 "
        "{%0,%1,%2,%3}, {%4,%5,%6,%7}, {%8,%9}, {%0,%1,%2,%3};"
        : "+f"(c[0]), "+f"(c[1]), "+f"(c[2]), "+f"(c[3])
        : "r"(a[0]), "r"(a[1]), "r"(a[2]), "r"(a[3]), "r"(b0), "r"(b1));
}

// ---- smem geometry: BK=32 bf16 rows of 64B data, pitch 80B (conflict-free) -----
#define PITCH 80
#define OFF_AH 0
#define OFF_AL 10240          // 128 rows * 80
#define OFF_BH 20480
#define OFF_BL 25600          // 64 rows * 80
#define STAGE_BYTES 30720
#define NSTAGE 3
#define SMEM_DYN (NSTAGE * STAGE_BYTES)   // 92160

// ---- small kernels --------------------------------------------------------------
__global__ void zero_counters_kernel() {
    int i = threadIdx.x;
    if (i < NEXP) { g_cnt[i] = 0; g_fill[i] = 0; }
}

__global__ void router_kernel(const float* __restrict__ x,
                              const float* __restrict__ Wr,
                              float* __restrict__ logits_out, int write_logits) {
    const int t = blockIdx.x;
    const int warp = threadIdx.x >> 5;
    const int lane = threadIdx.x & 31;
    __shared__ float slog[NEXP];
    const float* xr = x + (size_t)t * HID;
    const float* wr = Wr + (size_t)warp * HID;
    float s = 0.0f;
    #pragma unroll 4
    for (int i = lane; i < HID; i += 32) s += xr[i] * wr[i];
    #pragma unroll
    for (int o = 16; o > 0; o >>= 1) s += __shfl_xor_sync(0xffffffffu, s, o);
    if (lane == 0) slog[warp] = s;
    __syncthreads();
    if (write_logits && threadIdx.x < NEXP)
        logits_out[t * NEXP + threadIdx.x] = slog[threadIdx.x];
    if (threadIdx.x == 0) {
        float v0 = -1e30f; int i0 = 0;
        #pragma unroll
        for (int i = 0; i < NEXP; i++) if (slog[i] > v0) { v0 = slog[i]; i0 = i; }
        float v1 = -1e30f; int i1 = 0;
        #pragma unroll
        for (int i = 0; i < NEXP; i++)
            if (i != i0 && slog[i] > v1) { v1 = slog[i]; i1 = i; }
        float ex = expf(v1 - v0);
        float inv = 1.0f / (1.0f + ex);
        g_tidx[2 * t] = i0; g_tidx[2 * t + 1] = i1;
        g_tw[2 * t] = inv;  g_tw[2 * t + 1] = ex * inv;
        atomicAdd(&g_cnt[i0], 1);
        atomicAdd(&g_cnt[i1], 1);
    }
}

__global__ void offsets_kernel() {
    if (threadIdx.x == 0) {
        int o = 0;
        #pragma unroll
        for (int e = 0; e < NEXP; e++) { g_off[e] = o; o += g_cnt[e]; }
    }
}

__global__ void scatter_kernel(int T) {
    int t = blockIdx.x * blockDim.x + threadIdx.x;
    if (t >= T) return;
    #pragma unroll
    for (int j = 0; j < 2; j++) {
        int e = g_tidx[2 * t + j];
        int p = atomicAdd(&g_fill[e], 1);
        int slot = g_off[e] + p;
        g_perm[slot] = t;
        g_w[slot] = g_tw[2 * t + j];
        g_slot_of[2 * t + j] = slot;
    }
}

// fused fp32 -> (bf16 hi, bf16 lo) split over x, Wg, Wu, Wd
__device__ __forceinline__ void split4_store(const float4 v, u32* dh, u32* dl, int i) {
    __nv_bfloat162 A = __floats2bfloat162_rn(v.x, v.y);
    __nv_bfloat162 B = __floats2bfloat162_rn(v.z, v.w);
    __nv_bfloat162 Ar = __floats2bfloat162_rn(v.x - __low2float(A), v.y - __high2float(A));
    __nv_bfloat162 Br = __floats2bfloat162_rn(v.z - __low2float(B), v.w - __high2float(B));
    ((uint2*)dh)[i] = make_uint2(*(u32*)&A, *(u32*)&B);
    ((uint2*)dl)[i] = make_uint2(*(u32*)&Ar, *(u32*)&Br);
}

__global__ void split_all_kernel(const float* __restrict__ x,
                                 const float* __restrict__ Wg,
                                 const float* __restrict__ Wu,
                                 const float* __restrict__ Wd, int nx, int nw) {
    int i = blockIdx.x * blockDim.x + threadIdx.x;
    if (i < nx) {
        split4_store(((const float4*)x)[i], (u32*)g_Xh, (u32*)g_Xl, i);
    } else if (i < nx + nw) {
        int j = i - nx;
        split4_store(((const float4*)Wg)[j], (u32*)g_Wgh, (u32*)g_Wgl, j);
    } else if (i < nx + 2 * nw) {
        int j = i - nx - nw;
        split4_store(((const float4*)Wu)[j], (u32*)g_Wuh, (u32*)g_Wul, j);
    } else if (i < nx + 3 * nw) {
        int j = i - nx - 2 * nw;
        split4_store(((const float4*)Wd)[j], (u32*)g_Wdh, (u32*)g_Wdl, j);
    }
}

// ---- GEMM 1: gate+up. CTA: 128 slots x 32 inter (gate+up => 64 cols), K=2048 ----
__global__ __launch_bounds__(256, 2) void gateup_mma_kernel() {
    const int e   = blockIdx.z;
    const int cnt = g_cnt[e];
    const int m0  = blockIdx.y * 128;
    if (m0 >= cnt) return;
    const int rows = min(cnt - m0, 128);
    const int base = g_off[e] + m0;
    const int n0   = blockIdx.x * 32;

    extern __shared__ char dsm[];
    const u32 sm0 = smem_u32(dsm);

    const int tid  = threadIdx.x;
    const int lane = tid & 31;
    const int wid  = tid >> 5;
    const int wm   = wid >> 2;          // 0..1 -> 64 rows
    const int wn   = wid & 3;           // 0..3 -> 16 cols

    // ---- loader mapping: q = row-within-128, c = 16B chunk ----
    const int q = tid >> 2;             // 0..63
    const int c = tid & 3;
    const int r0 = min(q, rows - 1);
    const int r1 = min(q + 64, rows - 1);
    const size_t xo0 = (size_t)g_perm[base + r0] * HID + c * 8;
    const size_t xo1 = (size_t)g_perm[base + r1] * HID + c * 8;
    const __nv_bfloat16 *pbh, *pbl;
    if (q < 32) {
        const size_t wrow = ((size_t)e * INTER + n0 + q) * HID + c * 8;
        pbh = g_Wgh + wrow; pbl = g_Wgl + wrow;
    } else {
        const size_t wrow = ((size_t)e * INTER + n0 + (q - 32)) * HID + c * 8;
        pbh = g_Wuh + wrow; pbl = g_Wul + wrow;
    }
    const u32 dA0 = (u32)(OFF_AH + q * PITCH + c * 16);
    const u32 dA1 = dA0 + 64 * PITCH;
    const u32 dL0 = dA0 + (OFF_AL - OFF_AH);
    const u32 dL1 = dA1 + (OFF_AL - OFF_AH);
    const u32 dB  = (u32)(OFF_BH + q * PITCH + c * 16);
    const u32 dBl = dB + (OFF_BL - OFF_BH);

    // ---- ldmatrix bases ----
    const u32 a_off = (u32)((wm * 64 + (lane & 7) + ((lane >> 3) & 1) * 8) * PITCH
                    + (lane >> 4) * 16);
    const u32 b_off = (u32)((wn * 16 + (lane & 7) + (lane >> 4) * 8) * PITCH
                    + ((lane >> 3) & 1) * 16);

    float acc[4][2][4];
    #pragma unroll
    for (int i = 0; i < 4; i++)
        #pragma unroll
        for (int j = 0; j < 2; j++)
            #pragma unroll
            for (int k = 0; k < 4; k++) acc[i][j][k] = 0.0f;

    const int KT = HID / 32;            // 64

    #pragma unroll
    for (int p = 0; p < NSTAGE - 1; p++) {
        const u32 sb = sm0 + (u32)p * STAGE_BYTES;
        const size_t ko = (size_t)p * 32;
        cpa16(sb + dA0, g_Xh + xo0 + ko);
        cpa16(sb + dA1, g_Xh + xo1 + ko);
        cpa16(sb + dL0, g_Xl + xo0 + ko);
        cpa16(sb + dL1, g_Xl + xo1 + ko);
        cpa16(sb + dB,  pbh + ko);
        cpa16(sb + dBl, pbl + ko);
        CPA_COMMIT();
    }

    #pragma unroll 1
    for (int kt = 0; kt < KT; kt++) {
        if (kt == KT - 1) CPA_WAIT0(); else CPA_WAIT1();
        __syncthreads();
        if (kt + NSTAGE - 1 < KT) {
            const u32 sb = sm0 + (u32)((kt + NSTAGE - 1) % NSTAGE) * STAGE_BYTES;
            const size_t ko = (size_t)(kt + NSTAGE - 1) * 32;
            cpa16(sb + dA0, g_Xh + xo0 + ko);
            cpa16(sb + dA1, g_Xh + xo1 + ko);
            cpa16(sb + dL0, g_Xl + xo0 + ko);
            cpa16(sb + dL1, g_Xl + xo1 + ko);
            cpa16(sb + dB,  pbh + ko);
            cpa16(sb + dBl, pbl + ko);
            CPA_COMMIT();
        }
        const u32 sb = sm0 + (u32)(kt % NSTAGE) * STAGE_BYTES;
        #pragma unroll
        for (int ks = 0; ks < 2; ks++) {
            u32 ah[4][4], al[4][4], bh[4], bl[4];
            #pragma unroll
            for (int mi = 0; mi < 4; mi++) {
                ldsm4(ah[mi], sb + OFF_AH + a_off + (u32)(mi * 16 * PITCH) + (u32)(ks * 32));
                ldsm4(al[mi], sb + OFF_AL + a_off + (u32)(mi * 16 * PITCH) + (u32)(ks * 32));
            }
            ldsm4(bh, sb + OFF_BH + b_off + (u32)(ks * 32));
            ldsm4(bl, sb + OFF_BL + b_off + (u32)(ks * 32));
            #pragma unroll
            for (int mi = 0; mi < 4; mi++) {
                #pragma unroll
                for (int ni = 0; ni < 2; ni++) {
                    const int s = ni * 2;
                    mma16816(acc[mi][ni], ah[mi], bh[s], bh[s + 1]);
                    mma16816(acc[mi][ni], ah[mi], bl[s], bl[s + 1]);
                    mma16816(acc[mi][ni], al[mi], bh[s], bh[s + 1]);
                }
            }
        }
    }
    __syncthreads();

    // ---- epilogue: exchange via smem (128 x 72 f32), silu(g)*u, split hi/lo ----
    float* S = (float*)dsm;
    #pragma unroll
    for (int mi = 0; mi < 4; mi++) {
        const int rr = wm * 64 + mi * 16 + (lane >> 2);
        #pragma unroll
        for (int ni = 0; ni < 2; ni++) {
            const int cc = wn * 16 + ni * 8 + 2 * (lane & 3);
            *(float2*)(S + (size_t)rr * 72 + cc)       = make_float2(acc[mi][ni][0], acc[mi][ni][1]);
            *(float2*)(S + (size_t)(rr + 8) * 72 + cc) = make_float2(acc[mi][ni][2], acc[mi][ni][3]);
        }
    }
    __syncthreads();
    {
        const int row  = tid >> 1;
        const int half = (tid & 1) * 16;
        if (row < rows) {
            u32 ph[8], pl[8];
            #pragma unroll
            for (int p = 0; p < 8; p++) {
                float g0 = S[(size_t)row * 72 + half + 2 * p];
                float g1 = S[(size_t)row * 72 + half + 2 * p + 1];
                float u0 = S[(size_t)row * 72 + 32 + half + 2 * p];
                float u1 = S[(size_t)row * 72 + 32 + half + 2 * p + 1];
                float h0 = (g0 / (1.0f + expf(-g0))) * u0;
                float h1 = (g1 / (1.0f + expf(-g1))) * u1;
                __nv_bfloat162 A = __floats2bfloat162_rn(h0, h1);
                __nv_bfloat162 B = __floats2bfloat162_rn(h0 - __low2float(A), h1 - __high2float(A));
                ph[p] = *(u32*)&A;
                pl[p] = *(u32*)&B;
            }
            u32* dh = (u32*)(g_Hh + (size_t)(base + row) * INTER + n0 + half);
            u32* dl = (u32*)(g_Hl + (size_t)(base + row) * INTER + n0 + half);
            ((uint4*)dh)[0] = make_uint4(ph[0], ph[1], ph[2], ph[3]);
            ((uint4*)dh)[1] = make_uint4(ph[4], ph[5], ph[6], ph[7]);
            ((uint4*)dl)[0] = make_uint4(pl[0], pl[1], pl[2], pl[3]);
            ((uint4*)dl)[1] = make_uint4(pl[4], pl[5], pl[6], pl[7]);
        }
    }
}

// ---- GEMM 2: down. CTA: 128 slots x 64 hid, K=1024 -------------------------------
__global__ __launch_bounds__(256, 2) void down_mma_kernel() {
    const int e   = blockIdx.z;
    const int cnt = g_cnt[e];
    const int m0  = blockIdx.y * 128;
    if (m0 >= cnt) return;
    const int rows = min(cnt - m0, 128);
    const int base = g_off[e] + m0;
    const int n0   = blockIdx.x * 64;

    extern __shared__ char dsm[];
    const u32 sm0 = smem_u32(dsm);

    const int tid  = threadIdx.x;
    const int lane = tid & 31;
    const int wid  = tid >> 5;
    const int wm   = wid >> 2;
    const int wn   = wid & 3;

    const int q = tid >> 2;
    const int c = tid & 3;
    const int r0 = min(q, rows - 1);
    const int r1 = min(q + 64, rows - 1);
    const size_t ho0 = (size_t)(base + r0) * INTER + c * 8;
    const size_t ho1 = (size_t)(base + r1) * INTER + c * 8;
    const size_t wrow = ((size_t)e * HID + n0 + q) * INTER + c * 8;
    const __nv_bfloat16* pbh = g_Wdh + wrow;
    const __nv_bfloat16* pbl = g_Wdl + wrow;

    const u32 dA0 = (u32)(OFF_AH + q * PITCH + c * 16);
    const u32 dA1 = dA0 + 64 * PITCH;
    const u32 dL0 = dA0 + (OFF_AL - OFF_AH);
    const u32 dL1 = dA1 + (OFF_AL - OFF_AH);
    const u32 dB  = (u32)(OFF_BH + q * PITCH + c * 16);
    const u32 dBl = dB + (OFF_BL - OFF_BH);

    const u32 a_off = (u32)((wm * 64 + (lane & 7) + ((lane >> 3) & 1) * 8) * PITCH
                    + (lane >> 4) * 16);
    const u32 b_off = (u32)((wn * 16 + (lane & 7) + (lane >> 4) * 8) * PITCH
                    + ((lane >> 3) & 1) * 16);

    float acc[4][2][4];
    #pragma unroll
    for (int i = 0; i < 4; i++)
        #pragma unroll
        for (int j = 0; j < 2; j++)
            #pragma unroll
            for (int k = 0; k < 4; k++) acc[i][j][k] = 0.0f;

    const int KT = INTER / 32;          // 32

    #pragma unroll
    for (int p = 0; p < NSTAGE - 1; p++) {
        const u32 sb = sm0 + (u32)p * STAGE_BYTES;
        const size_t ko = (size_t)p * 32;
        cpa16(sb + dA0, g_Hh + ho0 + ko);
        cpa16(sb + dA1, g_Hh + ho1 + ko);
        cpa16(sb + dL0, g_Hl + ho0 + ko);
        cpa16(sb + dL1, g_Hl + ho1 + ko);
        cpa16(sb + dB,  pbh + ko);
        cpa16(sb + dBl, pbl + ko);
        CPA_COMMIT();
    }

    #pragma unroll 1
    for (int kt = 0; kt < KT; kt++) {
        if (kt == KT - 1) CPA_WAIT0(); else CPA_WAIT1();
        __syncthreads();
        if (kt + NSTAGE - 1 < KT) {
            const u32 sb = sm0 + (u32)((kt + NSTAGE - 1) % NSTAGE) * STAGE_BYTES;
            const size_t ko = (size_t)(kt + NSTAGE - 1) * 32;
            cpa16(sb + dA0, g_Hh + ho0 + ko);
            cpa16(sb + dA1, g_Hh + ho1 + ko);
            cpa16(sb + dL0, g_Hl + ho0 + ko);
            cpa16(sb + dL1, g_Hl + ho1 + ko);
            cpa16(sb + dB,  pbh + ko);
            cpa16(sb + dBl, pbl + ko);
            CPA_COMMIT();
        }
        const u32 sb = sm0 + (u32)(kt % NSTAGE) * STAGE_BYTES;
        #pragma unroll
        for (int ks = 0; ks < 2; ks++) {
            u32 ah[4][4], al[4][4], bh[4], bl[4];
            #pragma unroll
            for (int mi = 0; mi < 4; mi++) {
                ldsm4(ah[mi], sb + OFF_AH + a_off + (u32)(mi * 16 * PITCH) + (u32)(ks * 32));
                ldsm4(al[mi], sb + OFF_AL + a_off + (u32)(mi * 16 * PITCH) + (u32)(ks * 32));
            }
            ldsm4(bh, sb + OFF_BH + b_off + (u32)(ks * 32));
            ldsm4(bl, sb + OFF_BL + b_off + (u32)(ks * 32));
            #pragma unroll
            for (int mi = 0; mi < 4; mi++) {
                #pragma unroll
                for (int ni = 0; ni < 2; ni++) {
                    const int s = ni * 2;
                    mma16816(acc[mi][ni], ah[mi], bh[s], bh[s + 1]);
                    mma16816(acc[mi][ni], ah[mi], bl[s], bl[s + 1]);
                    mma16816(acc[mi][ni], al[mi], bh[s], bh[s + 1]);
                }
            }
        }
    }

    // ---- epilogue: scale by routing weight, store f32 ----
    #pragma unroll
    for (int mi = 0; mi < 4; mi++) {
        const int r0o = wm * 64 + mi * 16 + (lane >> 2);
        const int r1o = r0o + 8;
        #pragma unroll
        for (int ni = 0; ni < 2; ni++) {
            const int cc = n0 + wn * 16 + ni * 8 + 2 * (lane & 3);
            if (r0o < rows) {
                const float w0 = g_w[base + r0o];
                *(float2*)(g_y + (size_t)(base + r0o) * HID + cc) =
                    make_float2(w0 * acc[mi][ni][0], w0 * acc[mi][ni][1]);
            }
            if (r1o < rows) {
                const float w1 = g_w[base + r1o];
                *(float2*)(g_y + (size_t)(base + r1o) * HID + cc) =
                    make_float2(w1 * acc[mi][ni][2], w1 * acc[mi][ni][3]);
            }
        }
    }
}

// ---- combine: out[t] = y[slot0] + y[slot1] ----------------------------------------
__global__ void combine_kernel(float* __restrict__ out, int T) {
    const int gid = blockIdx.x * blockDim.x + threadIdx.x;
    const int per_tok = HID / 4;
    if (gid >= T * per_tok) return;
    const int t = gid / per_tok;
    const int c = gid - t * per_tok;
    const int s0 = g_slot_of[2 * t];
    const int s1 = g_slot_of[2 * t + 1];
    float4 a = ((const float4*)(g_y + (size_t)s0 * HID))[c];
    float4 b = ((const float4*)(g_y + (size_t)s1 * HID))[c];
    ((float4*)(out + (size_t)t * HID))[c] =
        make_float4(a.x + b.x, a.y + b.y, a.z + b.z, a.w + b.w);
}

// ---- launch -------------------------------------------------------------------------
extern "C" void kernel_launch(void* const* d_in, const int* in_sizes, int n_in,
                              void* d_out, int out_size) {
    if (n_in < 5) return;
    const float* x  = (const float*)d_in[0];
    const float* Wr = (const float*)d_in[1];
    const float* Wg = (const float*)d_in[2];
    const float* Wu = (const float*)d_in[3];
    const float* Wd = (const float*)d_in[4];
    float* out = (float*)d_out;

    int T = in_sizes[0] / HID;
    if (T > MAXT) T = MAXT;

    cudaFuncSetAttribute(gateup_mma_kernel, cudaFuncAttributeMaxDynamicSharedMemorySize, SMEM_DYN);
    cudaFuncSetAttribute(down_mma_kernel,   cudaFuncAttributeMaxDynamicSharedMemorySize, SMEM_DYN);

    const int write_logits = (out_size >= T * HID + T * NEXP);
    float* logits = out + (size_t)T * HID;

    zero_counters_kernel<<<1, 32>>>();
    router_kernel<<<T, 256>>>(x, Wr, logits, write_logits);
    offsets_kernel<<<1, 32>>>();
    scatter_kernel<<<(T + 255) / 256, 256>>>(T);

    const int nx = T * HID / 4;
    const int nw = NEXP * INTER * HID / 4;
    split_all_kernel<<<(nx + 3 * nw + 255) / 256, 256>>>(x, Wg, Wu, Wd, nx, nw);

    gateup_mma_kernel<<<dim3(INTER / 32, MAXSLOTS / 128, NEXP), 256, SMEM_DYN>>>();
    down_mma_kernel<<<dim3(HID / 64, MAXSLOTS / 128, NEXP), 256, SMEM_DYN>>>();

    combine_kernel<<<(T * (HID / 4) + 255) / 256, 256>>>(out, T);
}